// round 15
// baseline (speedup 1.0000x reference)
#include <cuda_runtime.h>

#define ED 2048
#define EDV 512          // float4s per row
#define NH 16
#define HD 128
#define LCACHE 8192
#define L1 8193
#define NCHUNK 2048                 // 4-row stream chunks
#define TICKETS_PER_EPOCH 2304u     // NCHUNK + 256 (one failing draw/block)

// scratch (no allocs allowed)
__device__ float g_q[ED];      // q = x@Wq + bq
__device__ float g_hsum[NH];   // sum of exp(score) over rows [0,8192)
__device__ float g_vals[ED];   // sum of exp(score)*v (rows [0,8192))
// monotonic counters (never reset -> replay-safe via epoch arithmetic)
__device__ unsigned g_enter;   // +256 per launch (epoch source)
__device__ unsigned g_qcnt;    // +256 per launch (q-slice arrivals)
__device__ unsigned g_ticket;  // +2304 per launch (stream work-stealing)
__device__ unsigned g_scnt;    // +256 per launch (stream done)

// ---------------------------------------------------------------------------
// ONE persistent kernel: 256 blocks x 512 threads, occ 2 -> all resident
// (256 < 2*148), so in-kernel spin barriers are deadlock-free.
//
// Per block:
//   stage x; block 0 zeroes accumulators and seeds out_i = bo.
//   1a: q cols [8b, 8b+8) over all 2048 rows -> g_q, arrive g_qcnt.
//   1b: k_i (b<128) or v_i cols [16(b&127), +16) -> k_tail / v_tail.
//   barrier 1: wait g_qcnt (q ready; own 1b already filled the wait).
//   2:  work-steal 4-row chunks via g_ticket: read k row -> score ->
//       copy out_k; read v row -> acc exp(s)*v -> copy out_v. Warp==head.
//   barrier 2: g_scnt (all stream atomics visible).
//   3:  redundant per-head tail weight e_h, sinv_h; oproj partial GEMV
//       block = (row-slice of 256) x (64-col group) over Wo,
//       x[i] = (g_vals[i] + e_h*v_tail[i])*sinv_h; atomicAdd into out_i.
// ---------------------------------------------------------------------------
__global__ void __launch_bounds__(512, 2)
mega_kernel(const float* __restrict__ kc, const float* __restrict__ vc,
            const float* __restrict__ x,
            const float* __restrict__ Wq, const float* __restrict__ bq,
            const float* __restrict__ Wk, const float* __restrict__ bk,
            const float* __restrict__ Wv, const float* __restrict__ bv,
            const float* __restrict__ Wo, const float* __restrict__ bo,
            float* __restrict__ out_k, float* __restrict__ out_v,
            float* __restrict__ k_tail, float* __restrict__ v_tail,
            float* __restrict__ out_i,
            float scale) {
    __shared__ float  sx[ED];
    __shared__ float4 sred[512];         // k/v proj reduction
    __shared__ float4 qred[16][2];       // q warp partials
    __shared__ float  sxs[256];
    __shared__ float  ssinv[NH];
    __shared__ float  se[NH];
    __shared__ unsigned s_epoch;
    __shared__ int s_chunk;

    int t = threadIdx.x;
    int b = blockIdx.x;
    int lane = t & 31;
    int wid = t >> 5;

    if (t == 0) s_epoch = atomicAdd(&g_enter, 1u) >> 8;
    for (int i = t; i < ED; i += 512) sx[i] = x[i];
    if (b == 0) {
        if (t < NH) g_hsum[t] = 0.f;
        for (int i = t; i < ED; i += 512) { g_vals[i] = 0.f; out_i[i] = bo[i]; }
    }
    __syncthreads();
    unsigned epoch = s_epoch;

    // ---------------- phase 1a: q slice (8 cols, all rows) ----------------
    {
        const float4* Wq4 = (const float4*)Wq;
        int f0 = b * 2;                  // two float4 columns per block
        float4 a0 = make_float4(0.f, 0.f, 0.f, 0.f);
        float4 a1 = make_float4(0.f, 0.f, 0.f, 0.f);
        int i0 = t * 4;
        #pragma unroll
        for (int r = 0; r < 4; ++r) {
            int i = i0 + r;
            float s = sx[i];
            float4 w0 = __ldcs(&Wq4[(size_t)i * EDV + f0]);
            float4 w1 = __ldcs(&Wq4[(size_t)i * EDV + f0 + 1]);
            a0.x += s * w0.x; a0.y += s * w0.y; a0.z += s * w0.z; a0.w += s * w0.w;
            a1.x += s * w1.x; a1.y += s * w1.y; a1.z += s * w1.z; a1.w += s * w1.w;
        }
        #pragma unroll
        for (int off = 16; off; off >>= 1) {
            a0.x += __shfl_xor_sync(0xffffffff, a0.x, off);
            a0.y += __shfl_xor_sync(0xffffffff, a0.y, off);
            a0.z += __shfl_xor_sync(0xffffffff, a0.z, off);
            a0.w += __shfl_xor_sync(0xffffffff, a0.w, off);
            a1.x += __shfl_xor_sync(0xffffffff, a1.x, off);
            a1.y += __shfl_xor_sync(0xffffffff, a1.y, off);
            a1.z += __shfl_xor_sync(0xffffffff, a1.z, off);
            a1.w += __shfl_xor_sync(0xffffffff, a1.w, off);
        }
        if (lane == 0) { qred[wid][0] = a0; qred[wid][1] = a1; }
        __syncthreads();
        if (t < 2) {
            float4 s = qred[0][t];
            #pragma unroll
            for (int w = 1; w < 16; ++w) {
                s.x += qred[w][t].x; s.y += qred[w][t].y;
                s.z += qred[w][t].z; s.w += qred[w][t].w;
            }
            float4 b4 = ((const float4*)bq)[f0 + t];
            s.x += b4.x; s.y += b4.y; s.z += b4.z; s.w += b4.w;
            ((float4*)g_q)[f0 + t] = s;
        }
        __threadfence();
        __syncthreads();
        if (t == 0) atomicAdd(&g_qcnt, 1u);
    }

    // ---------------- phase 1b: k_i / v_i slice (16 cols) ----------------
    {
        int m  = b >> 7;                 // 0 = k, 1 = v
        int fb = (b & 127) * 4;          // float4 col base
        const float* W  = m ? Wv : Wk;
        const float* bb = m ? bv : bk;
        float* dst      = m ? v_tail : k_tail;
        const float4* W4 = (const float4*)W;

        int f4c = t & 3;
        int rg  = t >> 2;                // 128 row-groups of 16 rows
        int jv  = fb + f4c;
        float4 acc = make_float4(0.f, 0.f, 0.f, 0.f);
        #pragma unroll
        for (int r = 0; r < 16; ++r) {
            int i = rg * 16 + r;
            float s = sx[i];
            float4 w = __ldcs(&W4[(size_t)i * EDV + jv]);
            acc.x += s * w.x; acc.y += s * w.y;
            acc.z += s * w.z; acc.w += s * w.w;
        }
        sred[t] = acc;
        __syncthreads();
        #pragma unroll
        for (int off = 256; off >= 4; off >>= 1) {
            if (t < off) {
                float4 o = sred[t + off];
                float4 s = sred[t];
                s.x += o.x; s.y += o.y; s.z += o.z; s.w += o.w;
                sred[t] = s;
            }
            __syncthreads();
        }
        if (t < 4) {
            float4 s = sred[t];
            float4 b4 = ((const float4*)bb)[fb + t];
            s.x += b4.x; s.y += b4.y; s.z += b4.z; s.w += b4.w;
            ((float4*)dst)[fb + t] = s;
        }
        __syncthreads();
    }

    // ---------------- barrier 1: q ready ----------------
    if (t == 0) {
        unsigned target = (epoch + 1u) * 256u;
        while (*(volatile unsigned*)&g_qcnt < target) __nanosleep(32);
    }
    __syncthreads();
    __threadfence();

    // ---------------- phase 2: work-stealing stream ----------------
    {
        int h = t >> 5;
        float4 q = ((const float4*)g_q)[t];
        unsigned base = epoch * TICKETS_PER_EPOCH;

        float lsum = 0.f;
        float cx = 0.f, cy = 0.f, cz = 0.f, cw = 0.f;
        for (;;) {
            if (t == 0) s_chunk = (int)(atomicAdd(&g_ticket, 1u) - base);
            __syncthreads();
            int ch = s_chunk;
            __syncthreads();
            if (ch >= NCHUNK) break;
            int l0 = ch * 4;
            const float4* ks = (const float4*)(kc + (size_t)l0 * ED);
            const float4* vs = (const float4*)(vc + (size_t)l0 * ED);
            float4* kd = (float4*)(out_k + (size_t)l0 * ED);
            float4* vd = (float4*)(out_v + (size_t)l0 * ED);

            float4 a[4], bb4[4];
            #pragma unroll
            for (int u = 0; u < 4; ++u) a[u]   = __ldcs(&ks[u * EDV + t]);
            #pragma unroll
            for (int u = 0; u < 4; ++u) bb4[u] = __ldcs(&vs[u * EDV + t]);
            #pragma unroll
            for (int u = 0; u < 4; ++u) __stcs(&kd[u * EDV + t], a[u]);
            float d[4];
            #pragma unroll
            for (int u = 0; u < 4; ++u)
                d[u] = a[u].x * q.x + a[u].y * q.y + a[u].z * q.z + a[u].w * q.w;
            #pragma unroll
            for (int off = 16; off; off >>= 1) {
                #pragma unroll
                for (int u = 0; u < 4; ++u)
                    d[u] += __shfl_xor_sync(0xffffffff, d[u], off);
            }
            #pragma unroll
            for (int u = 0; u < 4; ++u) __stcs(&vd[u * EDV + t], bb4[u]);
            #pragma unroll
            for (int u = 0; u < 4; ++u) {
                float p = expf(d[u] * scale);
                lsum += p;
                cx += p * bb4[u].x;
                cy += p * bb4[u].y;
                cz += p * bb4[u].z;
                cw += p * bb4[u].w;
            }
        }
        if (lane == 0) atomicAdd(&g_hsum[h], lsum);
        int c = 4 * t;
        atomicAdd(&g_vals[c],     cx);
        atomicAdd(&g_vals[c + 1], cy);
        atomicAdd(&g_vals[c + 2], cz);
        atomicAdd(&g_vals[c + 3], cw);
    }

    // ---------------- barrier 2: all stream contributions in ----------------
    __threadfence();
    __syncthreads();
    if (t == 0) {
        atomicAdd(&g_scnt, 1u);
        unsigned target = (epoch + 1u) * 256u;
        while (*(volatile unsigned*)&g_scnt < target) __nanosleep(32);
    }
    __syncthreads();
    __threadfence();

    // ---------------- phase 3: oproj ----------------
    {
        int h = t >> 5;
        float4 qv = ((const float4*)g_q)[t];
        float4 kt = ((const float4*)k_tail)[t];
        float d = qv.x * kt.x + qv.y * kt.y + qv.z * kt.z + qv.w * kt.w;
        #pragma unroll
        for (int off = 16; off; off >>= 1)
            d += __shfl_xor_sync(0xffffffff, d, off);
        if (lane == 0) {
            float e = expf(d * scale);
            se[h] = e;
            ssinv[h] = 1.f / (g_hsum[h] + e);
        }
        __syncthreads();

        int bi = b >> 5, bj = b & 31;
        int i0 = bi * 256;
        if (t < 256) {
            int gi = i0 + t;
            int hh = gi >> 7;
            sxs[t] = (g_vals[gi] + se[hh] * v_tail[gi]) * ssinv[hh];
        }
        __syncthreads();

        int jq = t & 15;
        int isub = t >> 4;
        int jv = bj * 16 + jq;
        const float4* W4 = (const float4*)Wo;
        int rbase = isub * 8;

        float4 acc = make_float4(0.f, 0.f, 0.f, 0.f);
        #pragma unroll
        for (int r = 0; r < 8; ++r) {
            float s = sxs[rbase + r];
            float4 w = __ldcs(&W4[(size_t)(i0 + rbase + r) * EDV + jv]);
            acc.x += s * w.x; acc.y += s * w.y;
            acc.z += s * w.z; acc.w += s * w.w;
        }
        sred[t] = acc;                    // reuse: [32 slices][16 cols]
        __syncthreads();
        if (t < 16) {
            float4 s = sred[t];
            #pragma unroll
            for (int u = 1; u < 32; ++u) {
                float4 o = sred[u * 16 + t];
                s.x += o.x; s.y += o.y; s.z += o.z; s.w += o.w;
            }
            int j = bj * 64 + t * 4;
            atomicAdd(&out_i[j],     s.x);
            atomicAdd(&out_i[j + 1], s.y);
            atomicAdd(&out_i[j + 2], s.z);
            atomicAdd(&out_i[j + 3], s.w);
        }
    }
}

extern "C" void kernel_launch(void* const* d_in, const int* in_sizes, int n_in,
                              void* d_out, int out_size) {
    const float* x  = (const float*)d_in[0];
    const float* v  = (const float*)d_in[1];
    const float* k  = (const float*)d_in[2];
    const float* Wv = (const float*)d_in[3];
    const float* bv = (const float*)d_in[4];
    const float* Wq = (const float*)d_in[5];
    const float* bq = (const float*)d_in[6];
    const float* Wk = (const float*)d_in[7];
    const float* bk = (const float*)d_in[8];
    const float* Wo = (const float*)d_in[9];
    const float* bo = (const float*)d_in[10];

    float* out   = (float*)d_out;
    float* out_i = out;                               // [2048]
    float* out_v = out + ED;                          // [8193, 2048]
    float* out_k = out_v + (size_t)L1 * ED;           // [8193, 2048]
    float* k_tail = out_k + (size_t)LCACHE * ED;
    float* v_tail = out_v + (size_t)LCACHE * ED;
    const float scale = 0.08838834764831845f;

    mega_kernel<<<256, 512>>>(k, v, x, Wq, bq, Wk, bk, Wv, bv, Wo, bo,
                              out_k, out_v, k_tail, v_tail, out_i, scale);
}